// round 1
// baseline (speedup 1.0000x reference)
#include <cuda_runtime.h>
#include <cuda_bf16.h>
#include <math.h>

#define BATCH   4
#define SEQ     2048
#define DM      768
#define DI      1536
#define DSTATE  64
#define DTR     48
#define XPD     (DTR + 2*DSTATE)   // 176
#define NTOK    (BATCH*SEQ)        // 8192

// ---------------- scratch (static device globals; no allocs) ----------------
__device__ __align__(256) float g_xz   [(size_t)NTOK * 2*DI];  // in_proj out [t, 3072]
__device__ __align__(256) float g_xconv[(size_t)NTOK * DI];    // silu(conv) [t, d]
__device__ __align__(256) float g_uT   [(size_t)BATCH*DI*SEQ]; // silu(conv) [b, d, t]
__device__ __align__(256) float g_xdbl [(size_t)NTOK * XPD];   // x_proj out [t, 176]
__device__ __align__(256) float g_dtT  [(size_t)BATCH*DI*SEQ]; // softplus dt [b, d, t]
__device__ __align__(256) float g_yT   [(size_t)BATCH*DI*SEQ]; // scan out   [b, d, t]
__device__ __align__(256) float g_gate [(size_t)NTOK * DI];    // gated y    [t, d]
__device__ __align__(256) float g_x1   [(size_t)NTOK * DM];    // layer-0 output

// ---------------- GEMM: C[M,N] = A[M,K](lda) * B[N,K]^T ----------------
// EPI 0: plain store. EPI 1: softplus(acc + bias[col]) stored transposed into
// dtT[b][col][t]  (row index = b*SEQ + t).
#define BM 128
#define BN 128
#define BKK 16

template<int EPI>
__global__ __launch_bounds__(256)
void gemm_nt(const float* __restrict__ A, int lda,
             const float* __restrict__ Bw,
             const float* __restrict__ bias,
             float* __restrict__ C,
             int M, int N, int K)
{
    __shared__ float As[BKK][BM + 4];
    __shared__ float Bs[BKK][BN + 4];

    const int tid = threadIdx.x;
    const int tx = tid & 15, ty = tid >> 4;
    const int rowBlk = blockIdx.y * BM;
    const int colBlk = blockIdx.x * BN;
    const int r0 = ty * 8, c0 = tx * 8;

    float acc[8][8];
#pragma unroll
    for (int i = 0; i < 8; i++)
#pragma unroll
        for (int j = 0; j < 8; j++) acc[i][j] = 0.f;

    for (int kt = 0; kt < K; kt += BKK) {
#pragma unroll
        for (int l = 0; l < 2; l++) {          // A tile: 128x16 as 512 float4
            int f = tid * 2 + l;
            int r = f >> 2, kf = (f & 3) * 4;
            float4 v = *(const float4*)&A[(size_t)(rowBlk + r) * lda + kt + kf];
            As[kf + 0][r] = v.x; As[kf + 1][r] = v.y;
            As[kf + 2][r] = v.z; As[kf + 3][r] = v.w;
        }
#pragma unroll
        for (int l = 0; l < 2; l++) {          // B tile: 128x16
            int f = tid * 2 + l;
            int r = f >> 2, kf = (f & 3) * 4;
            int n = colBlk + r;
            float4 v = make_float4(0.f, 0.f, 0.f, 0.f);
            if (n < N) v = *(const float4*)&Bw[(size_t)n * K + kt + kf];
            Bs[kf + 0][r] = v.x; Bs[kf + 1][r] = v.y;
            Bs[kf + 2][r] = v.z; Bs[kf + 3][r] = v.w;
        }
        __syncthreads();
#pragma unroll
        for (int k = 0; k < BKK; k++) {
            float a[8], b[8];
#pragma unroll
            for (int i = 0; i < 8; i++) a[i] = As[k][r0 + i];
#pragma unroll
            for (int j = 0; j < 8; j++) b[j] = Bs[k][c0 + j];
#pragma unroll
            for (int i = 0; i < 8; i++)
#pragma unroll
                for (int j = 0; j < 8; j++)
                    acc[i][j] = fmaf(a[i], b[j], acc[i][j]);
        }
        __syncthreads();
    }

    if (EPI == 0) {
#pragma unroll
        for (int i = 0; i < 8; i++) {
            int gr = rowBlk + r0 + i;
#pragma unroll
            for (int j = 0; j < 8; j++) {
                int gc = colBlk + c0 + j;
                if (gc < N) C[(size_t)gr * N + gc] = acc[i][j];
            }
        }
    } else {
#pragma unroll
        for (int j = 0; j < 8; j++) {
            int gc = colBlk + c0 + j;
            if (gc >= N) continue;
            float bv = bias[gc];
#pragma unroll
            for (int i = 0; i < 8; i++) {
                int gr = rowBlk + r0 + i;
                int b  = gr >> 11;          // SEQ = 2048
                int t  = gr & (SEQ - 1);
                float v = acc[i][j] + bv;
                v = (v > 20.f) ? v : log1pf(__expf(v));
                C[((size_t)b * DI + gc) * SEQ + t] = v;
            }
        }
    }
}

// ---------------- causal depthwise conv (K=4) + SiLU, dual-layout output ----
__global__ __launch_bounds__(1024)
void conv_silu_kernel(const float* __restrict__ xz,
                      const float* __restrict__ cw, const float* __restrict__ cb,
                      float* __restrict__ xconv, float* __restrict__ uT)
{
    __shared__ float xs[35][33];
    __shared__ float ys[32][33];
    const int tx = threadIdx.x, ty = threadIdx.y;
    const int t0 = blockIdx.x * 32, d0 = blockIdx.y * 32, b = blockIdx.z;

    for (int r = ty; r < 35; r += 32) {
        int t = t0 - 3 + r;
        xs[r][tx] = (t >= 0) ? xz[((size_t)b * SEQ + t) * (2 * DI) + d0 + tx] : 0.f;
    }
    __syncthreads();

    const int d = d0 + tx;
    const float w0 = cw[d * 4 + 0], w1 = cw[d * 4 + 1],
                w2 = cw[d * 4 + 2], w3 = cw[d * 4 + 3];
    float acc = cb[d];
    acc = fmaf(w0, xs[ty + 0][tx], acc);
    acc = fmaf(w1, xs[ty + 1][tx], acc);
    acc = fmaf(w2, xs[ty + 2][tx], acc);
    acc = fmaf(w3, xs[ty + 3][tx], acc);
    float v = acc / (1.f + __expf(-acc));        // silu

    xconv[((size_t)b * SEQ + t0 + ty) * DI + d] = v;
    ys[ty][tx] = v;
    __syncthreads();
    uT[((size_t)b * DI + d0 + ty) * SEQ + t0 + tx] = ys[tx][ty];
}

// ---------------- selective scan: one warp per (b, d) channel ----------------
__global__ __launch_bounds__(128)
void scan_kernel(const float* __restrict__ dtT, const float* __restrict__ uT,
                 const float* __restrict__ xdbl, const float* __restrict__ A_log,
                 float* __restrict__ yT)
{
    const int wid  = blockIdx.x * (blockDim.x >> 5) + (threadIdx.x >> 5);
    const int lane = threadIdx.x & 31;
    const int b = wid / DI;
    const int d = wid % DI;

    const float A0 = -__expf(A_log[(size_t)d * DSTATE + lane]);
    const float A1 = -__expf(A_log[(size_t)d * DSTATE + lane + 32]);
    float h0 = 0.f, h1 = 0.f;

    const float* dtp = dtT + ((size_t)b * DI + d) * SEQ;
    const float* up  = uT  + ((size_t)b * DI + d) * SEQ;
    float*       yp  = yT  + ((size_t)b * DI + d) * SEQ;

    for (int t0 = 0; t0 < SEQ; t0 += 32) {
        float dtc = dtp[t0 + lane];
        float uc  = up [t0 + lane];
        float ykeep = 0.f;
        const float* bc = xdbl + ((size_t)b * SEQ + t0) * XPD;
#pragma unroll 4
        for (int s = 0; s < 32; s++) {
            float dts = __shfl_sync(0xffffffffu, dtc, s);
            float us  = __shfl_sync(0xffffffffu, uc,  s);
            const float* row = bc + (size_t)s * XPD + DTR;
            float Bn0 = __ldg(row + lane);
            float Bn1 = __ldg(row + lane + 32);
            float Cn0 = __ldg(row + 64 + lane);
            float Cn1 = __ldg(row + 64 + lane + 32);
            float du = dts * us;
            h0 = fmaf(__expf(dts * A0), h0, du * Bn0);
            h1 = fmaf(__expf(dts * A1), h1, du * Bn1);
            float yv = fmaf(h0, Cn0, h1 * Cn1);
#pragma unroll
            for (int off = 16; off; off >>= 1)
                yv += __shfl_xor_sync(0xffffffffu, yv, off);
            if (lane == s) ykeep = yv;
        }
        yp[t0 + lane] = ykeep;
    }
}

// ---------------- gate: (y + D*u) * silu(z), transpose back to [t, d] -------
__global__ __launch_bounds__(1024)
void gate_kernel(const float* __restrict__ yT, const float* __restrict__ uT,
                 const float* __restrict__ Dp, const float* __restrict__ xz,
                 float* __restrict__ gate)
{
    __shared__ float s[32][33];
    const int tx = threadIdx.x, ty = threadIdx.y;
    const int t0 = blockIdx.x * 32, d0 = blockIdx.y * 32, b = blockIdx.z;

    size_t idx = ((size_t)b * DI + d0 + ty) * SEQ + t0 + tx;
    s[ty][tx] = yT[idx] + Dp[d0 + ty] * uT[idx];
    __syncthreads();

    const int t = t0 + ty, d = d0 + tx;
    float z  = xz[((size_t)b * SEQ + t) * (2 * DI) + DI + d];
    float sz = z / (1.f + __expf(-z));
    gate[((size_t)b * SEQ + t) * DI + d] = s[tx][ty] * sz;
}

// ---------------- host ----------------
extern "C" void kernel_launch(void* const* d_in, const int* in_sizes, int n_in,
                              void* d_out, int out_size)
{
    const float* x    = (const float*)d_in[0];
    const float* Wi   = (const float*)d_in[1];
    const float* cw   = (const float*)d_in[2];
    const float* cb   = (const float*)d_in[3];
    const float* Wx   = (const float*)d_in[4];
    const float* Wdt  = (const float*)d_in[5];
    const float* bdt  = (const float*)d_in[6];
    const float* Alog = (const float*)d_in[7];
    const float* Dp   = (const float*)d_in[8];
    const float* Wo   = (const float*)d_in[9];

    float *p_xz, *p_xconv, *p_uT, *p_xdbl, *p_dtT, *p_yT, *p_gate, *p_x1;
    cudaGetSymbolAddress((void**)&p_xz,    g_xz);
    cudaGetSymbolAddress((void**)&p_xconv, g_xconv);
    cudaGetSymbolAddress((void**)&p_uT,    g_uT);
    cudaGetSymbolAddress((void**)&p_xdbl,  g_xdbl);
    cudaGetSymbolAddress((void**)&p_dtT,   g_dtT);
    cudaGetSymbolAddress((void**)&p_yT,    g_yT);
    cudaGetSymbolAddress((void**)&p_gate,  g_gate);
    cudaGetSymbolAddress((void**)&p_x1,    g_x1);

    const float* cur = x;
    for (int l = 0; l < 2; l++) {
        const float* Wi_l  = Wi   + (size_t)l * 2 * DI * DM;
        const float* cw_l  = cw   + (size_t)l * DI * 4;
        const float* cb_l  = cb   + (size_t)l * DI;
        const float* Wx_l  = Wx   + (size_t)l * XPD * DI;
        const float* Wdt_l = Wdt  + (size_t)l * DI * DTR;
        const float* bdt_l = bdt  + (size_t)l * DI;
        const float* Al_l  = Alog + (size_t)l * DI * DSTATE;
        const float* Dp_l  = Dp   + (size_t)l * DI;
        const float* Wo_l  = Wo   + (size_t)l * DM * DI;
        float* out_l = (l == 1) ? (float*)d_out : p_x1;

        dim3 blk(256);
        dim3 g1((2 * DI) / BN, NTOK / BM);                 // 24 x 64
        gemm_nt<0><<<g1, blk>>>(cur, DM, Wi_l, nullptr, p_xz, NTOK, 2 * DI, DM);

        dim3 gc(SEQ / 32, DI / 32, BATCH);
        conv_silu_kernel<<<gc, dim3(32, 32)>>>(p_xz, cw_l, cb_l, p_xconv, p_uT);

        dim3 g2((XPD + BN - 1) / BN, NTOK / BM);           // 2 x 64
        gemm_nt<0><<<g2, blk>>>(p_xconv, DI, Wx_l, nullptr, p_xdbl, NTOK, XPD, DI);

        dim3 g3(DI / BN, NTOK / BM);                       // 12 x 64
        gemm_nt<1><<<g3, blk>>>(p_xdbl, XPD, Wdt_l, bdt_l, p_dtT, NTOK, DI, DTR);

        scan_kernel<<<(BATCH * DI) / 4, 128>>>(p_dtT, p_uT, p_xdbl, Al_l, p_yT);

        gate_kernel<<<gc, dim3(32, 32)>>>(p_yT, p_uT, Dp_l, p_xz, p_gate);

        dim3 g4(DM / BN, NTOK / BM);                       // 6 x 64
        gemm_nt<0><<<g4, blk>>>(p_gate, DI, Wo_l, nullptr, out_l, NTOK, DM, DI);

        cur = out_l;
    }
}

// round 2
// speedup vs baseline: 1.6059x; 1.6059x over previous
#include <cuda_runtime.h>
#include <cuda_bf16.h>
#include <math.h>
#include <stdint.h>

#define BATCH   4
#define SEQ     2048
#define DM      768
#define DI      1536
#define DSTATE  64
#define DTR     48
#define XPD     (DTR + 2*DSTATE)   // 176
#define NTOK    (BATCH*SEQ)        // 8192

// ---------------- scratch (static device globals; no allocs) ----------------
__device__ __align__(256) float g_xz   [(size_t)NTOK * 2*DI];  // in_proj out [t, 3072]
__device__ __align__(256) float g_xconv[(size_t)NTOK * DI];    // silu(conv) [t, d]
__device__ __align__(256) float g_uT   [(size_t)BATCH*DI*SEQ]; // silu(conv) [b, d, t]
__device__ __align__(256) float g_xdbl [(size_t)NTOK * XPD];   // x_proj out [t, 176]
__device__ __align__(256) float g_dtT  [(size_t)BATCH*DI*SEQ]; // softplus dt [b, d, t]
__device__ __align__(256) float g_yT   [(size_t)BATCH*DI*SEQ]; // scan out   [b, d, t]
__device__ __align__(256) float g_gate [(size_t)NTOK * DI];    // gated y    [t, d]
__device__ __align__(256) float g_x1   [(size_t)NTOK * DM];    // layer-0 output

// ---------------- TF32 helpers ----------------
__device__ __forceinline__ uint32_t f2tf32(float x) {
    uint32_t r;
    asm("cvt.rna.tf32.f32 %0, %1;" : "=r"(r) : "f"(x));
    return r;
}

__device__ __forceinline__ void mma_tf32(float* d, const uint32_t* a, const uint32_t* b) {
    asm volatile(
        "mma.sync.aligned.m16n8k8.row.col.f32.tf32.tf32.f32 "
        "{%0,%1,%2,%3}, {%4,%5,%6,%7}, {%8,%9}, {%0,%1,%2,%3};"
        : "+f"(d[0]), "+f"(d[1]), "+f"(d[2]), "+f"(d[3])
        : "r"(a[0]), "r"(a[1]), "r"(a[2]), "r"(a[3]), "r"(b[0]), "r"(b[1]));
}

// ---------------- TF32 tensor-core GEMM: C[M,N] = A[M,K](lda) * B[N,K]^T ----
// Block tile 128x128x32, 256 threads = 8 warps (2x4), warp tile 64x32.
// EPI 0: plain store. EPI 1: softplus(acc + bias[col]) stored transposed into
//        dtT[b][col][t], row index gr = b*SEQ + t.
//
// SMEM layouts (uint32 words, chosen for conflict-free LDS.64 fragment loads):
//  A: word(m,k) = k*136 + (m>>4)*16 + ((m&7)<<1) + ((m>>3)&1)
//     (rows m and m+8 interleaved as adjacent pair -> frag regs a0/a1 = LDS.64;
//      136 % 32 == 8 -> the 4 k-chunks of a quarter-warp hit disjoint banks)
//  B: word(n,k) = (k>>3)*1064 + (k&3)*264 + n*2 + ((k>>2)&1)
//     (k and k+4 adjacent -> b0/b1 = LDS.64; 264 % 32 == 8 -> disjoint banks)
#define AST 136
#define BST 264
#define BKS 1064

template<int EPI>
__global__ __launch_bounds__(256, 2)
void gemm_tf32(const float* __restrict__ A, int lda,
               const float* __restrict__ Bw,
               const float* __restrict__ bias,
               float* __restrict__ C,
               int M, int N, int K)
{
    __shared__ __align__(16) uint32_t As[32 * AST];
    __shared__ __align__(16) uint32_t Bs[4 * BKS];

    const int tid  = threadIdx.x;
    const int lane = tid & 31;
    const int wid  = tid >> 5;
    const int warpM = wid >> 2;          // 0..1
    const int warpN = wid & 3;           // 0..3
    const int rowBlk = blockIdx.y * 128;
    const int colBlk = blockIdx.x * 128;

    const int fc = lane & 3;             // fragment col-group
    const int fr = lane >> 2;            // fragment row-group

    float acc[4][4][4];
#pragma unroll
    for (int mt = 0; mt < 4; mt++)
#pragma unroll
        for (int nt = 0; nt < 4; nt++)
#pragma unroll
            for (int q = 0; q < 4; q++) acc[mt][nt][q] = 0.f;

    // global-load assignment: 2 threads per row, 16 k-floats each
    const int lrow = tid >> 1;            // 0..127
    const int lk0  = (tid & 1) * 16;      // 0 or 16
    const uint32_t paA = (lrow >> 4) * 16 + ((lrow & 7) << 1) + ((lrow >> 3) & 1);
    const int gn = colBlk + lrow;

    for (int kt = 0; kt < K; kt += 32) {
        // ---- A tile: 128 x 32 ----
#pragma unroll
        for (int j = 0; j < 4; j++) {
            int k = lk0 + 4 * j;
            float4 v = make_float4(0.f, 0.f, 0.f, 0.f);
            if (kt + k < K)
                v = *(const float4*)&A[(size_t)(rowBlk + lrow) * lda + kt + k];
            As[(k + 0) * AST + paA] = f2tf32(v.x);
            As[(k + 1) * AST + paA] = f2tf32(v.y);
            As[(k + 2) * AST + paA] = f2tf32(v.z);
            As[(k + 3) * AST + paA] = f2tf32(v.w);
        }
        // ---- B tile: 128 x 32 ----
#pragma unroll
        for (int j = 0; j < 4; j++) {
            int k = lk0 + 4 * j;
            float4 v = make_float4(0.f, 0.f, 0.f, 0.f);
            if (gn < N && kt + k < K)
                v = *(const float4*)&Bw[(size_t)gn * K + kt + k];
            float vv[4] = {v.x, v.y, v.z, v.w};
#pragma unroll
            for (int q = 0; q < 4; q++) {
                int kk = k + q;
                Bs[(kk >> 3) * BKS + (kk & 3) * BST + lrow * 2 + ((kk >> 2) & 1)] = f2tf32(vv[q]);
            }
        }
        __syncthreads();

#pragma unroll
        for (int ks = 0; ks < 4; ks++) {
            uint32_t afr[4][4];
#pragma unroll
            for (int mt = 0; mt < 4; mt++) {
                int mg = warpM * 64 + mt * 16;
                const uint32_t* p0 = &As[(ks * 8 + fc) * AST + mg + fr * 2];
                const uint32_t* p1 = &As[(ks * 8 + fc + 4) * AST + mg + fr * 2];
                uint2 v01 = *(const uint2*)p0;
                uint2 v23 = *(const uint2*)p1;
                afr[mt][0] = v01.x; afr[mt][1] = v01.y;
                afr[mt][2] = v23.x; afr[mt][3] = v23.y;
            }
            uint32_t bfr[4][2];
#pragma unroll
            for (int nt = 0; nt < 4; nt++) {
                int nb = warpN * 32 + nt * 8;
                uint2 v = *(const uint2*)&Bs[ks * BKS + fc * BST + (nb + fr) * 2];
                bfr[nt][0] = v.x; bfr[nt][1] = v.y;
            }
#pragma unroll
            for (int mt = 0; mt < 4; mt++)
#pragma unroll
                for (int nt = 0; nt < 4; nt++)
                    mma_tf32(acc[mt][nt], afr[mt], bfr[nt]);
        }
        __syncthreads();
    }

    // ---- epilogue ----
#pragma unroll
    for (int mt = 0; mt < 4; mt++) {
#pragma unroll
        for (int nt = 0; nt < 4; nt++) {
            int gr0 = rowBlk + warpM * 64 + mt * 16 + fr;
            int gc  = colBlk + warpN * 32 + nt * 8 + 2 * fc;
            if (EPI == 0) {
                if (gc < N) {
                    float2 lo = make_float2(acc[mt][nt][0], acc[mt][nt][1]);
                    float2 hi = make_float2(acc[mt][nt][2], acc[mt][nt][3]);
                    *(float2*)&C[(size_t)gr0 * N + gc]       = lo;
                    *(float2*)&C[(size_t)(gr0 + 8) * N + gc] = hi;
                }
            } else {
                if (gc < N) {
                    float bv0 = bias[gc], bv1 = bias[gc + 1];
#pragma unroll
                    for (int h = 0; h < 2; h++) {
                        int gr = gr0 + h * 8;
                        int b  = gr >> 11;            // SEQ = 2048
                        int t  = gr & (SEQ - 1);
                        float v0 = acc[mt][nt][h * 2 + 0] + bv0;
                        float v1 = acc[mt][nt][h * 2 + 1] + bv1;
                        v0 = (v0 > 20.f) ? v0 : log1pf(__expf(v0));
                        v1 = (v1 > 20.f) ? v1 : log1pf(__expf(v1));
                        C[((size_t)b * DI + gc)     * SEQ + t] = v0;
                        C[((size_t)b * DI + gc + 1) * SEQ + t] = v1;
                    }
                }
            }
        }
    }
}

// ---------------- causal depthwise conv (K=4) + SiLU, dual-layout output ----
__global__ __launch_bounds__(1024)
void conv_silu_kernel(const float* __restrict__ xz,
                      const float* __restrict__ cw, const float* __restrict__ cb,
                      float* __restrict__ xconv, float* __restrict__ uT)
{
    __shared__ float xs[35][33];
    __shared__ float ys[32][33];
    const int tx = threadIdx.x, ty = threadIdx.y;
    const int t0 = blockIdx.x * 32, d0 = blockIdx.y * 32, b = blockIdx.z;

    for (int r = ty; r < 35; r += 32) {
        int t = t0 - 3 + r;
        xs[r][tx] = (t >= 0) ? xz[((size_t)b * SEQ + t) * (2 * DI) + d0 + tx] : 0.f;
    }
    __syncthreads();

    const int d = d0 + tx;
    const float w0 = cw[d * 4 + 0], w1 = cw[d * 4 + 1],
                w2 = cw[d * 4 + 2], w3 = cw[d * 4 + 3];
    float acc = cb[d];
    acc = fmaf(w0, xs[ty + 0][tx], acc);
    acc = fmaf(w1, xs[ty + 1][tx], acc);
    acc = fmaf(w2, xs[ty + 2][tx], acc);
    acc = fmaf(w3, xs[ty + 3][tx], acc);
    float v = acc / (1.f + __expf(-acc));        // silu

    xconv[((size_t)b * SEQ + t0 + ty) * DI + d] = v;
    ys[ty][tx] = v;
    __syncthreads();
    uT[((size_t)b * DI + d0 + ty) * SEQ + t0 + tx] = ys[tx][ty];
}

// ---------------- selective scan: one warp per (b, d) channel ----------------
__global__ __launch_bounds__(128)
void scan_kernel(const float* __restrict__ dtT, const float* __restrict__ uT,
                 const float* __restrict__ xdbl, const float* __restrict__ A_log,
                 float* __restrict__ yT)
{
    const int wid  = blockIdx.x * (blockDim.x >> 5) + (threadIdx.x >> 5);
    const int lane = threadIdx.x & 31;
    const int b = wid / DI;
    const int d = wid % DI;

    const float A0 = -__expf(A_log[(size_t)d * DSTATE + lane]);
    const float A1 = -__expf(A_log[(size_t)d * DSTATE + lane + 32]);
    float h0 = 0.f, h1 = 0.f;

    const float* dtp = dtT + ((size_t)b * DI + d) * SEQ;
    const float* up  = uT  + ((size_t)b * DI + d) * SEQ;
    float*       yp  = yT  + ((size_t)b * DI + d) * SEQ;

    for (int t0 = 0; t0 < SEQ; t0 += 32) {
        float dtc = dtp[t0 + lane];
        float uc  = up [t0 + lane];
        float ykeep = 0.f;
        const float* bc = xdbl + ((size_t)b * SEQ + t0) * XPD;
#pragma unroll 4
        for (int s = 0; s < 32; s++) {
            float dts = __shfl_sync(0xffffffffu, dtc, s);
            float us  = __shfl_sync(0xffffffffu, uc,  s);
            const float* row = bc + (size_t)s * XPD + DTR;
            float Bn0 = __ldg(row + lane);
            float Bn1 = __ldg(row + lane + 32);
            float Cn0 = __ldg(row + 64 + lane);
            float Cn1 = __ldg(row + 64 + lane + 32);
            float du = dts * us;
            h0 = fmaf(__expf(dts * A0), h0, du * Bn0);
            h1 = fmaf(__expf(dts * A1), h1, du * Bn1);
            float yv = fmaf(h0, Cn0, h1 * Cn1);
#pragma unroll
            for (int off = 16; off; off >>= 1)
                yv += __shfl_xor_sync(0xffffffffu, yv, off);
            if (lane == s) ykeep = yv;
        }
        yp[t0 + lane] = ykeep;
    }
}

// ---------------- gate: (y + D*u) * silu(z), transpose back to [t, d] -------
__global__ __launch_bounds__(1024)
void gate_kernel(const float* __restrict__ yT, const float* __restrict__ uT,
                 const float* __restrict__ Dp, const float* __restrict__ xz,
                 float* __restrict__ gate)
{
    __shared__ float s[32][33];
    const int tx = threadIdx.x, ty = threadIdx.y;
    const int t0 = blockIdx.x * 32, d0 = blockIdx.y * 32, b = blockIdx.z;

    size_t idx = ((size_t)b * DI + d0 + ty) * SEQ + t0 + tx;
    s[ty][tx] = yT[idx] + Dp[d0 + ty] * uT[idx];
    __syncthreads();

    const int t = t0 + ty, d = d0 + tx;
    float z  = xz[((size_t)b * SEQ + t) * (2 * DI) + DI + d];
    float sz = z / (1.f + __expf(-z));
    gate[((size_t)b * SEQ + t) * DI + d] = s[tx][ty] * sz;
}

// ---------------- host ----------------
extern "C" void kernel_launch(void* const* d_in, const int* in_sizes, int n_in,
                              void* d_out, int out_size)
{
    const float* x    = (const float*)d_in[0];
    const float* Wi   = (const float*)d_in[1];
    const float* cw   = (const float*)d_in[2];
    const float* cb   = (const float*)d_in[3];
    const float* Wx   = (const float*)d_in[4];
    const float* Wdt  = (const float*)d_in[5];
    const float* bdt  = (const float*)d_in[6];
    const float* Alog = (const float*)d_in[7];
    const float* Dp   = (const float*)d_in[8];
    const float* Wo   = (const float*)d_in[9];

    float *p_xz, *p_xconv, *p_uT, *p_xdbl, *p_dtT, *p_yT, *p_gate, *p_x1;
    cudaGetSymbolAddress((void**)&p_xz,    g_xz);
    cudaGetSymbolAddress((void**)&p_xconv, g_xconv);
    cudaGetSymbolAddress((void**)&p_uT,    g_uT);
    cudaGetSymbolAddress((void**)&p_xdbl,  g_xdbl);
    cudaGetSymbolAddress((void**)&p_dtT,   g_dtT);
    cudaGetSymbolAddress((void**)&p_yT,    g_yT);
    cudaGetSymbolAddress((void**)&p_gate,  g_gate);
    cudaGetSymbolAddress((void**)&p_x1,    g_x1);

    const float* cur = x;
    for (int l = 0; l < 2; l++) {
        const float* Wi_l  = Wi   + (size_t)l * 2 * DI * DM;
        const float* cw_l  = cw   + (size_t)l * DI * 4;
        const float* cb_l  = cb   + (size_t)l * DI;
        const float* Wx_l  = Wx   + (size_t)l * XPD * DI;
        const float* Wdt_l = Wdt  + (size_t)l * DI * DTR;
        const float* bdt_l = bdt  + (size_t)l * DI;
        const float* Al_l  = Alog + (size_t)l * DI * DSTATE;
        const float* Dp_l  = Dp   + (size_t)l * DI;
        const float* Wo_l  = Wo   + (size_t)l * DM * DI;
        float* out_l = (l == 1) ? (float*)d_out : p_x1;

        dim3 blk(256);
        dim3 g1((2 * DI) / 128, NTOK / 128);               // 24 x 64
        gemm_tf32<0><<<g1, blk>>>(cur, DM, Wi_l, nullptr, p_xz, NTOK, 2 * DI, DM);

        dim3 gc(SEQ / 32, DI / 32, BATCH);
        conv_silu_kernel<<<gc, dim3(32, 32)>>>(p_xz, cw_l, cb_l, p_xconv, p_uT);

        dim3 g2((XPD + 127) / 128, NTOK / 128);            // 2 x 64
        gemm_tf32<0><<<g2, blk>>>(p_xconv, DI, Wx_l, nullptr, p_xdbl, NTOK, XPD, DI);

        dim3 g3(DI / 128, NTOK / 128);                     // 12 x 64
        gemm_tf32<1><<<g3, blk>>>(p_xdbl, XPD, Wdt_l, bdt_l, p_dtT, NTOK, DI, DTR);

        scan_kernel<<<(BATCH * DI) / 4, 128>>>(p_dtT, p_uT, p_xdbl, Al_l, p_yT);

        gate_kernel<<<gc, dim3(32, 32)>>>(p_yT, p_uT, Dp_l, p_xz, p_gate);

        dim3 g4(DM / 128, NTOK / 128);                     // 6 x 64
        gemm_tf32<0><<<g4, blk>>>(p_gate, DI, Wo_l, nullptr, out_l, NTOK, DM, DI);

        cur = out_l;
    }
}

// round 4
// speedup vs baseline: 1.6393x; 1.0208x over previous
#include <cuda_runtime.h>
#include <cuda_bf16.h>
#include <math.h>
#include <stdint.h>

#define BATCH   4
#define SEQ     2048
#define DM      768
#define DI      1536
#define DSTATE  64
#define DTR     48
#define XPD     (DTR + 2*DSTATE)   // 176
#define XPDP    256                // padded N for x_proj weight
#define DTKP    64                 // padded K for dt GEMM (48 -> 64)
#define NTOK    (BATCH*SEQ)        // 8192

typedef __nv_bfloat16 bf16;

// ---------------- scratch (static device globals; zero-initialized) ---------
__device__ __align__(256) float g_xz   [(size_t)NTOK * 2*DI];
__device__ __align__(256) float g_uT   [(size_t)BATCH*DI*SEQ];
__device__ __align__(256) float g_xdbl [(size_t)NTOK * XPD];
__device__ __align__(256) float g_dtT  [(size_t)BATCH*DI*SEQ];
__device__ __align__(256) float g_yT   [(size_t)BATCH*DI*SEQ];

// bf16 hi/lo operand buffers (pads stay zero forever: zero-init, never written)
__device__ __align__(256) bf16 g_x0h[(size_t)NTOK*DM],  g_x0l[(size_t)NTOK*DM];
__device__ __align__(256) bf16 g_x1h[(size_t)NTOK*DM],  g_x1l[(size_t)NTOK*DM];
__device__ __align__(256) bf16 g_xch[(size_t)NTOK*DI],  g_xcl[(size_t)NTOK*DI];
__device__ __align__(256) bf16 g_dah[(size_t)NTOK*DTKP],g_dal[(size_t)NTOK*DTKP];
__device__ __align__(256) bf16 g_gth[(size_t)NTOK*DI],  g_gtl[(size_t)NTOK*DI];
__device__ __align__(256) bf16 g_wih[2][(size_t)2*DI*DM],     g_wil[2][(size_t)2*DI*DM];
__device__ __align__(256) bf16 g_wxh[2][(size_t)XPDP*DI],     g_wxl[2][(size_t)XPDP*DI];
__device__ __align__(256) bf16 g_wdh[2][(size_t)DI*DTKP],     g_wdl[2][(size_t)DI*DTKP];
__device__ __align__(256) bf16 g_woh[2][(size_t)DM*DI],       g_wol[2][(size_t)DM*DI];

// ---------------- helpers ----------------
__device__ __forceinline__ void split_bf(float x, bf16& h, bf16& l) {
    h = __float2bfloat16(x);
    l = __float2bfloat16(x - __bfloat162float(h));
}

__device__ __forceinline__ void cpasync16(uint32_t dst, const void* src) {
    asm volatile("cp.async.cg.shared.global [%0], [%1], 16;" :: "r"(dst), "l"(src));
}

__device__ __forceinline__ void ldsm_x4(uint32_t& r0, uint32_t& r1, uint32_t& r2, uint32_t& r3, uint32_t a) {
    asm volatile("ldmatrix.sync.aligned.m8n8.x4.shared.b16 {%0,%1,%2,%3}, [%4];"
                 : "=r"(r0), "=r"(r1), "=r"(r2), "=r"(r3) : "r"(a));
}
__device__ __forceinline__ void ldsm_x2(uint32_t& r0, uint32_t& r1, uint32_t a) {
    asm volatile("ldmatrix.sync.aligned.m8n8.x2.shared.b16 {%0,%1}, [%2];"
                 : "=r"(r0), "=r"(r1) : "r"(a));
}
__device__ __forceinline__ void mma_bf16(float* d, const uint32_t* a, const uint32_t* b) {
    asm volatile(
        "mma.sync.aligned.m16n8k16.row.col.f32.bf16.bf16.f32 "
        "{%0,%1,%2,%3}, {%4,%5,%6,%7}, {%8,%9}, {%0,%1,%2,%3};"
        : "+f"(d[0]), "+f"(d[1]), "+f"(d[2]), "+f"(d[3])
        : "r"(a[0]), "r"(a[1]), "r"(a[2]), "r"(a[3]), "r"(b[0]), "r"(b[1]));
}

// ---------------- generic f32 -> (hi, lo) bf16 split ----------------
__global__ __launch_bounds__(256)
void split_kernel(const float* __restrict__ in, int in_ld, int rows, int cols,
                  bf16* __restrict__ H, bf16* __restrict__ L, int out_ld)
{
    int i = blockIdx.x * 256 + threadIdx.x;
    if (i >= rows * cols) return;
    int r = i / cols, c = i - r * cols;
    float x = in[(size_t)r * in_ld + c];
    bf16 h, l; split_bf(x, h, l);
    H[(size_t)r * out_ld + c] = h;
    L[(size_t)r * out_ld + c] = l;
}

// ---------------- bf16x3 GEMM: C[M,N] = (Ah+Al)[M,K] * (Bh+Bl)[N,K]^T -------
// Block 128x128x32, 256 thr (8 warps 2x4), warp 64x32, cp.async double-buffer.
// Tile in smem: [128 rows][32 k bf16 = 64B], 16B-group swizzle:
//   off(row, kg) = row*64 + 16*(kg ^ ((row>>1)&3)),  kg = k/8 in [0,4)
// EPI 0: C f32.  EPI 1: softplus(acc+bias[col]) transposed into dtT layout.
// EPI 2: C f32 + (hi,lo) into Ho/Lo[ldh] for col < hcols.  EPI 3: (hi,lo) only.
#define TILEB 8192          // bytes per operand tile
#define STAGEB (4*TILEB)    // Ah, Al, Bh, Bl

template<int EPI>
__global__ __launch_bounds__(256, 2)
void gemm_bf16x3(const bf16* __restrict__ Ah, const bf16* __restrict__ Al, int lda,
                 const bf16* __restrict__ Bh, const bf16* __restrict__ Bl,
                 const float* __restrict__ bias,
                 float* __restrict__ C, int N,
                 bf16* __restrict__ Ho, bf16* __restrict__ Lo, int ldh, int hcols,
                 int K)
{
    extern __shared__ __align__(16) uint8_t smem[];
    const uint32_t smbase = (uint32_t)__cvta_generic_to_shared(smem);

    const int tid  = threadIdx.x;
    const int lane = tid & 31;
    const int wid  = tid >> 5;
    const int warpM = wid >> 2;          // 0..1
    const int warpN = wid & 3;           // 0..3
    const int rowBlk = blockIdx.y * 128;
    const int colBlk = blockIdx.x * 128;
    const int fr = lane >> 2, fc = lane & 3;

    float acc[4][4][4];
#pragma unroll
    for (int mt = 0; mt < 4; mt++)
#pragma unroll
        for (int nt = 0; nt < 4; nt++)
#pragma unroll
            for (int q = 0; q < 4; q++) acc[mt][nt][q] = 0.f;

    // ---- cp.async assignment: each thread: 1 row, 2 adjacent 16B k-groups ----
    const int lrow = tid >> 1;
    const int kg0  = (tid & 1) * 2;
    const int swz  = (lrow >> 1) & 3;
    const uint32_t dst0 = lrow * 64 + ((kg0 ^ swz) << 4);
    const uint32_t dst1 = lrow * 64 + (((kg0 + 1) ^ swz) << 4);
    const bf16* gAh = Ah + (size_t)(rowBlk + lrow) * lda + kg0 * 8;
    const bf16* gAl = Al + (size_t)(rowBlk + lrow) * lda + kg0 * 8;
    const bf16* gBh = Bh + (size_t)(colBlk + lrow) * K + kg0 * 8;
    const bf16* gBl = Bl + (size_t)(colBlk + lrow) * K + kg0 * 8;

    // ---- fragment address precompute ----
    uint32_t arow[4], asw[4], brow[4], bsw[4];
#pragma unroll
    for (int mt = 0; mt < 4; mt++) {
        int r = warpM * 64 + mt * 16 + (lane & 15);
        arow[mt] = r * 64; asw[mt] = (r >> 1) & 3;
    }
#pragma unroll
    for (int nt = 0; nt < 4; nt++) {
        int n = warpN * 32 + nt * 8 + (lane & 7);
        brow[nt] = n * 64; bsw[nt] = (n >> 1) & 3;
    }
    const int akg = lane >> 4;          // 0/1: which 16B group within k16
    const int bkg = (lane >> 3) & 1;

    const int nk = K >> 5;

    // prologue: stage 0
    {
        uint32_t s = smbase;
        cpasync16(s + dst0,             gAh);
        cpasync16(s + dst1,             gAh + 8);
        cpasync16(s + TILEB   + dst0,   gAl);
        cpasync16(s + TILEB   + dst1,   gAl + 8);
        cpasync16(s + 2*TILEB + dst0,   gBh);
        cpasync16(s + 2*TILEB + dst1,   gBh + 8);
        cpasync16(s + 3*TILEB + dst0,   gBl);
        cpasync16(s + 3*TILEB + dst1,   gBl + 8);
        asm volatile("cp.async.commit_group;");
    }

    for (int it = 0; it < nk; it++) {
        if (it + 1 < nk) {
            uint32_t s = smbase + ((it + 1) & 1) * STAGEB;
            int ko = (it + 1) * 32;
            cpasync16(s + dst0,             gAh + ko);
            cpasync16(s + dst1,             gAh + ko + 8);
            cpasync16(s + TILEB   + dst0,   gAl + ko);
            cpasync16(s + TILEB   + dst1,   gAl + ko + 8);
            cpasync16(s + 2*TILEB + dst0,   gBh + ko);
            cpasync16(s + 2*TILEB + dst1,   gBh + ko + 8);
            cpasync16(s + 3*TILEB + dst0,   gBl + ko);
            cpasync16(s + 3*TILEB + dst1,   gBl + ko + 8);
        }
        asm volatile("cp.async.commit_group;");
        asm volatile("cp.async.wait_group 1;");
        __syncthreads();

        const uint32_t sA = smbase + (it & 1) * STAGEB;
        const uint32_t sB = sA + 2*TILEB;
#pragma unroll
        for (int ks = 0; ks < 2; ks++) {
            uint32_t bh[4][2], bl[4][2];
#pragma unroll
            for (int nt = 0; nt < 4; nt++) {
                uint32_t off = brow[nt] + (((ks * 2 + bkg) ^ bsw[nt]) << 4);
                ldsm_x2(bh[nt][0], bh[nt][1], sB + off);
                ldsm_x2(bl[nt][0], bl[nt][1], sB + TILEB + off);
            }
#pragma unroll
            for (int mt = 0; mt < 4; mt++) {
                uint32_t off = arow[mt] + (((ks * 2 + akg) ^ asw[mt]) << 4);
                uint32_t ah[4], al[4];
                ldsm_x4(ah[0], ah[1], ah[2], ah[3], sA + off);
                ldsm_x4(al[0], al[1], al[2], al[3], sA + TILEB + off);
#pragma unroll
                for (int nt = 0; nt < 4; nt++) {
                    mma_bf16(acc[mt][nt], ah, bh[nt]);
                    mma_bf16(acc[mt][nt], ah, bl[nt]);
                    mma_bf16(acc[mt][nt], al, bh[nt]);
                }
            }
        }
        __syncthreads();
    }

    // ---- epilogue ----
#pragma unroll
    for (int mt = 0; mt < 4; mt++) {
#pragma unroll
        for (int nt = 0; nt < 4; nt++) {
            int gr0 = rowBlk + warpM * 64 + mt * 16 + fr;
            int gc  = colBlk + warpN * 32 + nt * 8 + 2 * fc;
            if (EPI == 0) {
                if (gc < N) {
                    *(float2*)&C[(size_t)gr0 * N + gc] =
                        make_float2(acc[mt][nt][0], acc[mt][nt][1]);
                    *(float2*)&C[(size_t)(gr0 + 8) * N + gc] =
                        make_float2(acc[mt][nt][2], acc[mt][nt][3]);
                }
            } else if (EPI == 1) {
                if (gc < N) {
                    float bv0 = bias[gc], bv1 = bias[gc + 1];
#pragma unroll
                    for (int h = 0; h < 2; h++) {
                        int gr = gr0 + h * 8;
                        int b  = gr >> 11, t = gr & (SEQ - 1);
                        float v0 = acc[mt][nt][h * 2 + 0] + bv0;
                        float v1 = acc[mt][nt][h * 2 + 1] + bv1;
                        v0 = (v0 > 20.f) ? v0 : log1pf(__expf(v0));
                        v1 = (v1 > 20.f) ? v1 : log1pf(__expf(v1));
                        C[((size_t)b * DI + gc)     * SEQ + t] = v0;
                        C[((size_t)b * DI + gc + 1) * SEQ + t] = v1;
                    }
                }
            } else if (EPI == 2) {
#pragma unroll
                for (int h = 0; h < 2; h++) {
                    int gr = gr0 + h * 8;
                    float v0 = acc[mt][nt][h * 2 + 0];
                    float v1 = acc[mt][nt][h * 2 + 1];
                    if (gc < N) {
                        C[(size_t)gr * N + gc]     = v0;
                        C[(size_t)gr * N + gc + 1] = v1;
                    }
                    if (gc < hcols) {
                        bf16 h0, l0, h1, l1;
                        split_bf(v0, h0, l0); split_bf(v1, h1, l1);
                        Ho[(size_t)gr * ldh + gc]     = h0;
                        Lo[(size_t)gr * ldh + gc]     = l0;
                        Ho[(size_t)gr * ldh + gc + 1] = h1;
                        Lo[(size_t)gr * ldh + gc + 1] = l1;
                    }
                }
            } else {   // EPI 3
#pragma unroll
                for (int h = 0; h < 2; h++) {
                    int gr = gr0 + h * 8;
                    bf16 h0, l0, h1, l1;
                    split_bf(acc[mt][nt][h * 2 + 0], h0, l0);
                    split_bf(acc[mt][nt][h * 2 + 1], h1, l1);
                    Ho[(size_t)gr * ldh + gc]     = h0;
                    Lo[(size_t)gr * ldh + gc]     = l0;
                    Ho[(size_t)gr * ldh + gc + 1] = h1;
                    Lo[(size_t)gr * ldh + gc + 1] = l1;
                }
            }
        }
    }
}

// ---------------- causal depthwise conv (K=4) + SiLU ----------------
// outputs: uT f32 [b,d,t]  +  (hi,lo) bf16 [t,d]
__global__ __launch_bounds__(1024)
void conv_silu_kernel(const float* __restrict__ xz,
                      const float* __restrict__ cw, const float* __restrict__ cb,
                      bf16* __restrict__ xch, bf16* __restrict__ xcl,
                      float* __restrict__ uT)
{
    __shared__ float xs[35][33];
    __shared__ float ys[32][33];
    const int tx = threadIdx.x, ty = threadIdx.y;
    const int t0 = blockIdx.x * 32, d0 = blockIdx.y * 32, b = blockIdx.z;

    for (int r = ty; r < 35; r += 32) {
        int t = t0 - 3 + r;
        xs[r][tx] = (t >= 0) ? xz[((size_t)b * SEQ + t) * (2 * DI) + d0 + tx] : 0.f;
    }
    __syncthreads();

    const int d = d0 + tx;
    const float w0 = cw[d * 4 + 0], w1 = cw[d * 4 + 1],
                w2 = cw[d * 4 + 2], w3 = cw[d * 4 + 3];
    float acc = cb[d];
    acc = fmaf(w0, xs[ty + 0][tx], acc);
    acc = fmaf(w1, xs[ty + 1][tx], acc);
    acc = fmaf(w2, xs[ty + 2][tx], acc);
    acc = fmaf(w3, xs[ty + 3][tx], acc);
    float v = acc / (1.f + __expf(-acc));

    bf16 h, l; split_bf(v, h, l);
    size_t oi = ((size_t)b * SEQ + t0 + ty) * DI + d;
    xch[oi] = h; xcl[oi] = l;
    ys[ty][tx] = v;
    __syncthreads();
    uT[((size_t)b * DI + d0 + ty) * SEQ + t0 + tx] = ys[tx][ty];
}

// ---------------- selective scan: one warp per (b, d) channel ----------------
__global__ __launch_bounds__(128)
void scan_kernel(const float* __restrict__ dtT, const float* __restrict__ uT,
                 const float* __restrict__ xdbl, const float* __restrict__ A_log,
                 float* __restrict__ yT)
{
    const int wid  = blockIdx.x * (blockDim.x >> 5) + (threadIdx.x >> 5);
    const int lane = threadIdx.x & 31;
    const int b = wid / DI;
    const int d = wid % DI;

    const float A0 = -__expf(A_log[(size_t)d * DSTATE + lane]);
    const float A1 = -__expf(A_log[(size_t)d * DSTATE + lane + 32]);
    float h0 = 0.f, h1 = 0.f;

    const float* dtp = dtT + ((size_t)b * DI + d) * SEQ;
    const float* up  = uT  + ((size_t)b * DI + d) * SEQ;
    float*       yp  = yT  + ((size_t)b * DI + d) * SEQ;

    for (int t0 = 0; t0 < SEQ; t0 += 32) {
        float dtc = dtp[t0 + lane];
        float uc  = up [t0 + lane];
        float ykeep = 0.f;
        const float* bc = xdbl + ((size_t)b * SEQ + t0) * XPD;
#pragma unroll 4
        for (int s = 0; s < 32; s++) {
            float dts = __shfl_sync(0xffffffffu, dtc, s);
            float us  = __shfl_sync(0xffffffffu, uc,  s);
            const float* row = bc + (size_t)s * XPD + DTR;
            float Bn0 = __ldg(row + lane);
            float Bn1 = __ldg(row + lane + 32);
            float Cn0 = __ldg(row + 64 + lane);
            float Cn1 = __ldg(row + 64 + lane + 32);
            float du = dts * us;
            h0 = fmaf(__expf(dts * A0), h0, du * Bn0);
            h1 = fmaf(__expf(dts * A1), h1, du * Bn1);
            float yv = fmaf(h0, Cn0, h1 * Cn1);
#pragma unroll
            for (int off = 16; off; off >>= 1)
                yv += __shfl_xor_sync(0xffffffffu, yv, off);
            if (lane == s) ykeep = yv;
        }
        yp[t0 + lane] = ykeep;
    }
}

// ---------------- gate: (y + D*u) * silu(z) -> (hi, lo) bf16 [t, d] ---------
__global__ __launch_bounds__(1024)
void gate_kernel(const float* __restrict__ yT, const float* __restrict__ uT,
                 const float* __restrict__ Dp, const float* __restrict__ xz,
                 bf16* __restrict__ gth, bf16* __restrict__ gtl)
{
    __shared__ float s[32][33];
    const int tx = threadIdx.x, ty = threadIdx.y;
    const int t0 = blockIdx.x * 32, d0 = blockIdx.y * 32, b = blockIdx.z;

    size_t idx = ((size_t)b * DI + d0 + ty) * SEQ + t0 + tx;
    s[ty][tx] = yT[idx] + Dp[d0 + ty] * uT[idx];
    __syncthreads();

    const int t = t0 + ty, d = d0 + tx;
    float z  = xz[((size_t)b * SEQ + t) * (2 * DI) + DI + d];
    float sz = z / (1.f + __expf(-z));
    float v  = s[tx][ty] * sz;
    bf16 h, l; split_bf(v, h, l);
    size_t oi = ((size_t)b * SEQ + t) * DI + d;
    gth[oi] = h; gtl[oi] = l;
}

// ---------------- host ----------------
static inline int cdiv(int a, int b) { return (a + b - 1) / b; }

extern "C" void kernel_launch(void* const* d_in, const int* in_sizes, int n_in,
                              void* d_out, int out_size)
{
    const float* x    = (const float*)d_in[0];
    const float* Wi   = (const float*)d_in[1];
    const float* cw   = (const float*)d_in[2];
    const float* cb   = (const float*)d_in[3];
    const float* Wx   = (const float*)d_in[4];
    const float* Wdt  = (const float*)d_in[5];
    const float* bdt  = (const float*)d_in[6];
    const float* Alog = (const float*)d_in[7];
    const float* Dp   = (const float*)d_in[8];
    const float* Wo   = (const float*)d_in[9];

    float *p_xz, *p_uT, *p_xdbl, *p_dtT, *p_yT;
    cudaGetSymbolAddress((void**)&p_xz,   g_xz);
    cudaGetSymbolAddress((void**)&p_uT,   g_uT);
    cudaGetSymbolAddress((void**)&p_xdbl, g_xdbl);
    cudaGetSymbolAddress((void**)&p_dtT,  g_dtT);
    cudaGetSymbolAddress((void**)&p_yT,   g_yT);

    bf16 *x0h, *x0l, *x1h, *x1l, *xch, *xcl, *dah, *dal, *gth, *gtl;
    bf16 *wih, *wil, *wxh, *wxl, *wdh, *wdl, *woh, *wol;
    cudaGetSymbolAddress((void**)&x0h, g_x0h); cudaGetSymbolAddress((void**)&x0l, g_x0l);
    cudaGetSymbolAddress((void**)&x1h, g_x1h); cudaGetSymbolAddress((void**)&x1l, g_x1l);
    cudaGetSymbolAddress((void**)&xch, g_xch); cudaGetSymbolAddress((void**)&xcl, g_xcl);
    cudaGetSymbolAddress((void**)&dah, g_dah); cudaGetSymbolAddress((void**)&dal, g_dal);
    cudaGetSymbolAddress((void**)&gth, g_gth); cudaGetSymbolAddress((void**)&gtl, g_gtl);
    cudaGetSymbolAddress((void**)&wih, g_wih); cudaGetSymbolAddress((void**)&wil, g_wil);
    cudaGetSymbolAddress((void**)&wxh, g_wxh); cudaGetSymbolAddress((void**)&wxl, g_wxl);
    cudaGetSymbolAddress((void**)&wdh, g_wdh); cudaGetSymbolAddress((void**)&wdl, g_wdl);
    cudaGetSymbolAddress((void**)&woh, g_woh); cudaGetSymbolAddress((void**)&wol, g_wol);

    cudaFuncSetAttribute(gemm_bf16x3<0>, cudaFuncAttributeMaxDynamicSharedMemorySize, 2*STAGEB);
    cudaFuncSetAttribute(gemm_bf16x3<1>, cudaFuncAttributeMaxDynamicSharedMemorySize, 2*STAGEB);
    cudaFuncSetAttribute(gemm_bf16x3<2>, cudaFuncAttributeMaxDynamicSharedMemorySize, 2*STAGEB);
    cudaFuncSetAttribute(gemm_bf16x3<3>, cudaFuncAttributeMaxDynamicSharedMemorySize, 2*STAGEB);

    // ---- splits: input x and all weights ----
    split_kernel<<<cdiv(NTOK*DM, 256), 256>>>(x, DM, NTOK, DM, x0h, x0l, DM);
    for (int l = 0; l < 2; l++) {
        split_kernel<<<cdiv(2*DI*DM, 256), 256>>>(Wi + (size_t)l*2*DI*DM, DM, 2*DI, DM,
                                                  wih + (size_t)l*2*DI*DM, wil + (size_t)l*2*DI*DM, DM);
        split_kernel<<<cdiv(XPD*DI, 256), 256>>>(Wx + (size_t)l*XPD*DI, DI, XPD, DI,
                                                 wxh + (size_t)l*XPDP*DI, wxl + (size_t)l*XPDP*DI, DI);
        split_kernel<<<cdiv(DI*DTR, 256), 256>>>(Wdt + (size_t)l*DI*DTR, DTR, DI, DTR,
                                                 wdh + (size_t)l*DI*DTKP, wdl + (size_t)l*DI*DTKP, DTKP);
        split_kernel<<<cdiv(DM*DI, 256), 256>>>(Wo + (size_t)l*DM*DI, DI, DM, DI,
                                                woh + (size_t)l*DM*DI, wol + (size_t)l*DM*DI, DI);
    }

    const bf16* curh = x0h;
    const bf16* curl = x0l;
    for (int l = 0; l < 2; l++) {
        const float* cw_l  = cw   + (size_t)l * DI * 4;
        const float* cb_l  = cb   + (size_t)l * DI;
        const float* bdt_l = bdt  + (size_t)l * DI;
        const float* Al_l  = Alog + (size_t)l * DI * DSTATE;
        const float* Dp_l  = Dp   + (size_t)l * DI;

        dim3 blk(256);
        // in_proj: [8192 x 3072] = x * Wi^T
        gemm_bf16x3<0><<<dim3(24, 64), blk, 2*STAGEB>>>(
            curh, curl, DM, wih + (size_t)l*2*DI*DM, wil + (size_t)l*2*DI*DM,
            nullptr, p_xz, 2*DI, nullptr, nullptr, 0, 0, DM);

        dim3 gc(SEQ / 32, DI / 32, BATCH);
        conv_silu_kernel<<<gc, dim3(32, 32)>>>(p_xz, cw_l, cb_l, xch, xcl, p_uT);

        // x_proj: [8192 x 176], also emits (hi,lo) of first 48 cols into dt-A (ld 64)
        gemm_bf16x3<2><<<dim3(2, 64), blk, 2*STAGEB>>>(
            xch, xcl, DI, wxh + (size_t)l*XPDP*DI, wxl + (size_t)l*XPDP*DI,
            nullptr, p_xdbl, XPD, dah, dal, DTKP, DTR, DI);

        // dt: [8192 x 1536], K padded to 64; softplus+bias, transposed store
        gemm_bf16x3<1><<<dim3(12, 64), blk, 2*STAGEB>>>(
            dah, dal, DTKP, wdh + (size_t)l*DI*DTKP, wdl + (size_t)l*DI*DTKP,
            bdt_l, p_dtT, DI, nullptr, nullptr, 0, 0, DTKP);

        scan_kernel<<<(BATCH * DI) / 4, 128>>>(p_dtT, p_uT, p_xdbl, Al_l, p_yT);

        gate_kernel<<<gc, dim3(32, 32)>>>(p_yT, p_uT, Dp_l, p_xz, gth, gtl);

        // out_proj: [8192 x 768]
        if (l == 0) {
            gemm_bf16x3<3><<<dim3(6, 64), blk, 2*STAGEB>>>(
                gth, gtl, DI, woh + (size_t)l*DM*DI, wol + (size_t)l*DM*DI,
                nullptr, nullptr, DM, x1h, x1l, DM, DM, DI);
            curh = x1h; curl = x1l;
        } else {
            gemm_bf16x3<0><<<dim3(6, 64), blk, 2*STAGEB>>>(
                gth, gtl, DI, woh + (size_t)l*DM*DI, wol + (size_t)l*DM*DI,
                nullptr, (float*)d_out, DM, nullptr, nullptr, 0, 0, DI);
        }
    }
}